// round 1
// baseline (speedup 1.0000x reference)
#include <cuda_runtime.h>
#include <math.h>

// DeepSeek MoE: X[8192,1024], shared MLP 1024->512->1024 (SiLU),
// routing top-2 of 8 experts with sqrt(softplus) weights, routed MLPs same shape.
// out = shared_mlp(X) + sum_k w_k * expert_mlp_{e_k}(X)

namespace {
constexpr int NTOK = 8192;
constexpr int D    = 1024;
constexpr int HD   = 512;
constexpr int NE   = 8;
constexpr int BM = 128, BN = 128, BK = 8;
// 2*NTOK assignments + per-expert padding to BM multiples (<= 8*(BM-1))
constexpr int CAP  = 17408;   // divisible by BM (17408/128 = 136)
}

__device__ int   g_counts[NE];
__device__ int   g_offsets[NE + 1];
__device__ int   g_cursor[NE];
__device__ int   g_perm[CAP];
__device__ float g_wgt[CAP];
__device__ int   g_tok_e[NTOK * 2];
__device__ float g_tok_w[NTOK * 2];
__device__ float g_Hs[NTOK * HD];          // shared-expert hidden
__device__ float g_Hr[(size_t)CAP * HD];   // routed hidden (slot-major)

__global__ void init_kernel() {
    int i = blockIdx.x * blockDim.x + threadIdx.x;
    if (i < NE) g_counts[i] = 0;
    if (i < CAP) { g_perm[i] = 0; g_wgt[i] = 0.0f; }
}

__global__ void routing_kernel(const float* __restrict__ X,
                               const float* __restrict__ RW,
                               const float* __restrict__ EB) {
    int warp = (blockIdx.x * blockDim.x + threadIdx.x) >> 5;
    int lane = threadIdx.x & 31;
    if (warp >= NTOK) return;
    const float* x = X + (size_t)warp * D;
    float acc[NE];
#pragma unroll
    for (int e = 0; e < NE; e++) acc[e] = 0.0f;
    for (int k = lane; k < D; k += 32) {
        float xv = x[k];
#pragma unroll
        for (int e = 0; e < NE; e++) acc[e] = fmaf(xv, RW[e * D + k], acc[e]);
    }
#pragma unroll
    for (int e = 0; e < NE; e++) {
#pragma unroll
        for (int o = 16; o > 0; o >>= 1)
            acc[e] += __shfl_down_sync(0xffffffffu, acc[e], o);
    }
    if (lane == 0) {
        float act[NE];
#pragma unroll
        for (int e = 0; e < NE; e++) {
            float l = acc[e] + EB[e];
            // stable softplus
            float sp = (l > 0.0f) ? (l + log1pf(expf(-l))) : log1pf(expf(l));
            act[e] = sqrtf(sp);
        }
        // top-2, ties -> lowest index (matches jax top_k)
        int i0 = 0;
#pragma unroll
        for (int e = 1; e < NE; e++) if (act[e] > act[i0]) i0 = e;
        int i1 = (i0 == 0) ? 1 : 0;
#pragma unroll
        for (int e = 0; e < NE; e++)
            if (e != i0 && act[e] > act[i1]) i1 = e;
        g_tok_e[2 * warp + 0] = i0; g_tok_w[2 * warp + 0] = act[i0];
        g_tok_e[2 * warp + 1] = i1; g_tok_w[2 * warp + 1] = act[i1];
        atomicAdd(&g_counts[i0], 1);
        atomicAdd(&g_counts[i1], 1);
    }
}

__global__ void prefix_kernel() {
    if (threadIdx.x == 0 && blockIdx.x == 0) {
        int off = 0;
        for (int e = 0; e < NE; e++) {
            g_offsets[e] = off;
            g_cursor[e]  = off;
            off += ((g_counts[e] + BM - 1) / BM) * BM;  // pad to tile multiple
        }
        g_offsets[NE] = off;
    }
}

__global__ void scatter_kernel() {
    int i = blockIdx.x * blockDim.x + threadIdx.x;
    if (i >= NTOK * 2) return;
    int e = g_tok_e[i];
    int slot = atomicAdd(&g_cursor[e], 1);
    g_perm[slot] = i >> 1;
    g_wgt[slot]  = g_tok_w[i];
}

__device__ __forceinline__ float silu(float v) {
    return v / (1.0f + expf(-v));
}

// MODE 0: shared L1  : Hs[row]   = silu(X[row] @ W + b)
// MODE 1: routed L1  : Hr[slot]  = silu(X[perm[slot]] @ W_e + b_e)
// MODE 2: shared L2  : out[row]  = Hs[row] @ W + b          (plain store)
// MODE 3: routed L2  : out[perm[slot]] += w[slot]*(Hr[slot] @ W_e + b_e)  (atomicAdd)
template <int MODE, int KDIM, int NDIM>
__global__ void __launch_bounds__(256)
gemm_kernel(const float* __restrict__ A,
            const float* __restrict__ W,
            const float* __restrict__ bias,
            float* __restrict__ out) {
    __shared__ __align__(16) float As[BK][BM];
    __shared__ __align__(16) float Bs[BK][BN];
    __shared__ int   s_row[BM];
    __shared__ int   s_tok[BM];
    __shared__ float s_w[BM];

    const int tid     = threadIdx.x;          // 256 threads
    const int rowTile = blockIdx.y * BM;
    const int colTile = blockIdx.x * BN;

    const float* Wb = W;
    const float* bb = bias;
    if (MODE == 1 || MODE == 3) {
        int e = 0;
#pragma unroll
        for (int i = 1; i < NE; i++) if (rowTile >= g_offsets[i]) e = i;
        Wb = W + (size_t)e * KDIM * NDIM;
        bb = bias + e * NDIM;
    }

    const float* Abase;
    if (MODE == 2)      Abase = g_Hs;
    else if (MODE == 3) Abase = g_Hr;
    else                Abase = A;

    if (tid < BM) {
        int r = rowTile + tid;
        if (MODE == 1) {
            s_row[tid] = g_perm[r];
        } else if (MODE == 3) {
            s_row[tid] = r;
            s_tok[tid] = g_perm[r];
            s_w[tid]   = g_wgt[r];
        } else {
            s_row[tid] = r;
        }
    }
    __syncthreads();

    float acc[8][8];
#pragma unroll
    for (int i = 0; i < 8; i++)
#pragma unroll
        for (int j = 0; j < 8; j++) acc[i][j] = 0.0f;

    const int ty = tid >> 4;          // 0..15
    const int tx = tid & 15;          // 0..15
    const int arow = tid >> 1;        // 0..127
    const int akq  = (tid & 1) * 4;   // 0 or 4
    const int bk   = tid >> 5;        // 0..7
    const int bn   = (tid & 31) * 4;  // 0..124

    for (int kt = 0; kt < KDIM; kt += BK) {
        float4 av = *reinterpret_cast<const float4*>(
            Abase + (size_t)s_row[arow] * KDIM + kt + akq);
        As[akq + 0][arow] = av.x;
        As[akq + 1][arow] = av.y;
        As[akq + 2][arow] = av.z;
        As[akq + 3][arow] = av.w;
        float4 bv = *reinterpret_cast<const float4*>(
            Wb + (size_t)(kt + bk) * NDIM + colTile + bn);
        *reinterpret_cast<float4*>(&Bs[bk][bn]) = bv;
        __syncthreads();
#pragma unroll
        for (int k = 0; k < BK; k++) {
            float a[8], b[8];
            *reinterpret_cast<float4*>(&a[0]) = *reinterpret_cast<float4*>(&As[k][ty * 8]);
            *reinterpret_cast<float4*>(&a[4]) = *reinterpret_cast<float4*>(&As[k][ty * 8 + 4]);
            *reinterpret_cast<float4*>(&b[0]) = *reinterpret_cast<float4*>(&Bs[k][tx * 8]);
            *reinterpret_cast<float4*>(&b[4]) = *reinterpret_cast<float4*>(&Bs[k][tx * 8 + 4]);
#pragma unroll
            for (int i = 0; i < 8; i++)
#pragma unroll
                for (int j = 0; j < 8; j++)
                    acc[i][j] = fmaf(a[i], b[j], acc[i][j]);
        }
        __syncthreads();
    }

    // epilogue
#pragma unroll
    for (int i = 0; i < 8; i++) {
        const int m    = ty * 8 + i;
        const int grow = rowTile + m;
#pragma unroll
        for (int j = 0; j < 8; j += 4) {
            const int col = colTile + tx * 8 + j;
            float v0 = acc[i][j + 0] + bb[col + 0];
            float v1 = acc[i][j + 1] + bb[col + 1];
            float v2 = acc[i][j + 2] + bb[col + 2];
            float v3 = acc[i][j + 3] + bb[col + 3];
            if (MODE == 0 || MODE == 1) {
                v0 = silu(v0); v1 = silu(v1); v2 = silu(v2); v3 = silu(v3);
                float* dst = (MODE == 0 ? g_Hs : g_Hr);
                float4 vv = make_float4(v0, v1, v2, v3);
                *reinterpret_cast<float4*>(dst + (size_t)grow * NDIM + col) = vv;
            } else if (MODE == 2) {
                float4 vv = make_float4(v0, v1, v2, v3);
                *reinterpret_cast<float4*>(out + (size_t)grow * NDIM + col) = vv;
            } else { // MODE 3
                const float w = s_w[m];
                float* dst = out + (size_t)s_tok[m] * NDIM + col;
                atomicAdd(dst + 0, w * v0);
                atomicAdd(dst + 1, w * v1);
                atomicAdd(dst + 2, w * v2);
                atomicAdd(dst + 3, w * v3);
            }
        }
    }
}

extern "C" void kernel_launch(void* const* d_in, const int* in_sizes, int n_in,
                              void* d_out, int out_size) {
    (void)in_sizes; (void)n_in; (void)out_size;
    const float* X   = (const float*)d_in[0];
    const float* RW  = (const float*)d_in[1];
    const float* EB  = (const float*)d_in[2];
    const float* sW1 = (const float*)d_in[3];
    const float* sb1 = (const float*)d_in[4];
    const float* sW2 = (const float*)d_in[5];
    const float* sb2 = (const float*)d_in[6];
    const float* rW1 = (const float*)d_in[7];
    const float* rb1 = (const float*)d_in[8];
    const float* rW2 = (const float*)d_in[9];
    const float* rb2 = (const float*)d_in[10];
    float* out = (float*)d_out;

    init_kernel<<<(CAP + 255) / 256, 256>>>();
    routing_kernel<<<NTOK / 8, 256>>>(X, RW, EB);
    prefix_kernel<<<1, 32>>>();
    scatter_kernel<<<(NTOK * 2) / 256, 256>>>();

    // shared L1: Hs = silu(X @ sW1 + sb1)
    gemm_kernel<0, D, HD><<<dim3(HD / BN, NTOK / BM), 256>>>(X, sW1, sb1, nullptr);
    // routed L1: Hr = silu(X[perm] @ rW1[e] + rb1[e])
    gemm_kernel<1, D, HD><<<dim3(HD / BN, CAP / BM), 256>>>(X, rW1, rb1, nullptr);
    // shared L2: out = Hs @ sW2 + sb2
    gemm_kernel<2, HD, D><<<dim3(D / BN, NTOK / BM), 256>>>(nullptr, sW2, sb2, out);
    // routed L2: out[tok] += w * (Hr @ rW2[e] + rb2[e])
    gemm_kernel<3, HD, D><<<dim3(D / BN, CAP / BM), 256>>>(nullptr, rW2, rb2, out);
}

// round 3
// speedup vs baseline: 2.2424x; 2.2424x over previous
#include <cuda_runtime.h>
#include <cuda_bf16.h>
#include <cstdint>
#include <math.h>

namespace {
constexpr int NTOK = 8192;
constexpr int D    = 1024;
constexpr int HD   = 512;
constexpr int NE   = 8;
constexpr int BM = 128, BN = 128;
constexpr int CAP  = 17408;   // 2*NTOK + per-expert pad to 128, /128 = 136
}

__device__ int   g_counts[NE];
__device__ int   g_offsets[NE + 1];
__device__ int   g_cursor[NE];
__device__ int   g_perm[CAP];
__device__ float g_wgt[CAP];
__device__ int   g_tok_e[NTOK * 2];
__device__ float g_tok_w[NTOK * 2];

// split-bf16 operand buffers
__device__ __nv_bfloat16 g_Xh[NTOK * D],  g_Xl[NTOK * D];
__device__ __nv_bfloat16 g_sW1h[D * HD],  g_sW1l[D * HD];
__device__ __nv_bfloat16 g_sW2h[HD * D],  g_sW2l[HD * D];
__device__ __nv_bfloat16 g_rW1h[NE * D * HD], g_rW1l[NE * D * HD];
__device__ __nv_bfloat16 g_rW2h[NE * HD * D], g_rW2l[NE * HD * D];
__device__ __nv_bfloat16 g_Hsh[NTOK * HD], g_Hsl[NTOK * HD];
__device__ __nv_bfloat16 g_Hrh[(size_t)CAP * HD], g_Hrl[(size_t)CAP * HD];

__global__ void init_kernel() {
    int i = blockIdx.x * blockDim.x + threadIdx.x;
    if (i < NE) g_counts[i] = 0;
    if (i < CAP) { g_perm[i] = 0; g_wgt[i] = 0.0f; }
}

__global__ void routing_kernel(const float* __restrict__ X,
                               const float* __restrict__ RW,
                               const float* __restrict__ EB) {
    int warp = (blockIdx.x * blockDim.x + threadIdx.x) >> 5;
    int lane = threadIdx.x & 31;
    if (warp >= NTOK) return;
    const float* x = X + (size_t)warp * D;
    float acc[NE];
#pragma unroll
    for (int e = 0; e < NE; e++) acc[e] = 0.0f;
    for (int k = lane; k < D; k += 32) {
        float xv = x[k];
#pragma unroll
        for (int e = 0; e < NE; e++) acc[e] = fmaf(xv, RW[e * D + k], acc[e]);
    }
#pragma unroll
    for (int e = 0; e < NE; e++) {
#pragma unroll
        for (int o = 16; o > 0; o >>= 1)
            acc[e] += __shfl_down_sync(0xffffffffu, acc[e], o);
    }
    if (lane == 0) {
        float act[NE];
#pragma unroll
        for (int e = 0; e < NE; e++) {
            float l = acc[e] + EB[e];
            float sp = (l > 0.0f) ? (l + log1pf(expf(-l))) : log1pf(expf(l));
            act[e] = sqrtf(sp);
        }
        int i0 = 0;
#pragma unroll
        for (int e = 1; e < NE; e++) if (act[e] > act[i0]) i0 = e;
        int i1 = (i0 == 0) ? 1 : 0;
#pragma unroll
        for (int e = 0; e < NE; e++)
            if (e != i0 && act[e] > act[i1]) i1 = e;
        g_tok_e[2 * warp + 0] = i0; g_tok_w[2 * warp + 0] = act[i0];
        g_tok_e[2 * warp + 1] = i1; g_tok_w[2 * warp + 1] = act[i1];
        atomicAdd(&g_counts[i0], 1);
        atomicAdd(&g_counts[i1], 1);
    }
}

__global__ void prefix_kernel() {
    if (threadIdx.x == 0 && blockIdx.x == 0) {
        int off = 0;
        for (int e = 0; e < NE; e++) {
            g_offsets[e] = off;
            g_cursor[e]  = off;
            off += ((g_counts[e] + BM - 1) / BM) * BM;
        }
        g_offsets[NE] = off;
    }
}

__global__ void scatter_kernel() {
    int i = blockIdx.x * blockDim.x + threadIdx.x;
    if (i >= NTOK * 2) return;
    int e = g_tok_e[i];
    int slot = atomicAdd(&g_cursor[e], 1);
    g_perm[slot] = i >> 1;
    g_wgt[slot]  = g_tok_w[i];
}

// split fp32 -> (hi, lo) bf16
__global__ void cvt_kernel(const float* __restrict__ src, int n, int sel) {
    int i = (blockIdx.x * blockDim.x + threadIdx.x) * 2;
    if (i >= n) return;
    float2 v = *reinterpret_cast<const float2*>(src + i);
    __nv_bfloat16 h0 = __float2bfloat16(v.x);
    __nv_bfloat16 h1 = __float2bfloat16(v.y);
    __nv_bfloat16 l0 = __float2bfloat16(v.x - __bfloat162float(h0));
    __nv_bfloat16 l1 = __float2bfloat16(v.y - __bfloat162float(h1));
    __nv_bfloat16 *hp, *lp;
    switch (sel) {
        case 0:  hp = g_Xh;   lp = g_Xl;   break;
        case 1:  hp = g_sW1h; lp = g_sW1l; break;
        case 2:  hp = g_sW2h; lp = g_sW2l; break;
        case 3:  hp = g_rW1h; lp = g_rW1l; break;
        default: hp = g_rW2h; lp = g_rW2l; break;
    }
    *reinterpret_cast<__nv_bfloat162*>(hp + i) = __halves2bfloat162(h0, h1);
    *reinterpret_cast<__nv_bfloat162*>(lp + i) = __halves2bfloat162(l0, l1);
}

__device__ __forceinline__ float silu(float v) { return v / (1.0f + expf(-v)); }

__device__ __forceinline__ void ldsm4(uint32_t (&r)[4], uint32_t addr) {
    asm volatile("ldmatrix.sync.aligned.m8n8.x4.shared.b16 {%0,%1,%2,%3}, [%4];\n"
        : "=r"(r[0]), "=r"(r[1]), "=r"(r[2]), "=r"(r[3]) : "r"(addr));
}
__device__ __forceinline__ void ldsm4t(uint32_t (&r)[4], uint32_t addr) {
    asm volatile("ldmatrix.sync.aligned.m8n8.x4.trans.shared.b16 {%0,%1,%2,%3}, [%4];\n"
        : "=r"(r[0]), "=r"(r[1]), "=r"(r[2]), "=r"(r[3]) : "r"(addr));
}
__device__ __forceinline__ void mma_bf16(float (&c)[4], const uint32_t (&a)[4],
                                         uint32_t b0, uint32_t b1) {
    asm volatile(
        "mma.sync.aligned.m16n8k16.row.col.f32.bf16.bf16.f32 "
        "{%0,%1,%2,%3}, {%4,%5,%6,%7}, {%8,%9}, {%0,%1,%2,%3};\n"
        : "+f"(c[0]), "+f"(c[1]), "+f"(c[2]), "+f"(c[3])
        : "r"(a[0]), "r"(a[1]), "r"(a[2]), "r"(a[3]), "r"(b0), "r"(b1));
}

// MODE 0: shared L1 -> Hs(hi/lo)   MODE 1: routed L1 -> Hr(hi/lo)
// MODE 2: shared L2 -> out (store) MODE 3: routed L2 -> out (atomicAdd w*y)
template <int MODE, int KDIM, int NDIM>
__device__ __forceinline__ void mma_gemm_body(const float* __restrict__ bias,
                                              float* __restrict__ out) {
    __shared__ __align__(16) __nv_bfloat16 sA[2][2][128][24];  // [stage][hi/lo][m][k]
    __shared__ __align__(16) __nv_bfloat16 sB[2][2][16][136];  // [stage][hi/lo][k][n]
    __shared__ int   s_row[128];
    __shared__ int   s_tok[128];
    __shared__ float s_w[128];

    const int tid = threadIdx.x;
    const int rowTile = blockIdx.y * BM;
    const int colTile = blockIdx.x * BN;

    const __nv_bfloat16 *Wh, *Wl;
    const float* bb = bias;
    if constexpr (MODE == 0)      { Wh = g_sW1h; Wl = g_sW1l; }
    else if constexpr (MODE == 2) { Wh = g_sW2h; Wl = g_sW2l; }
    else {
        int e = 0;
#pragma unroll
        for (int i = 1; i < NE; i++) if (rowTile >= g_offsets[i]) e = i;
        size_t off = (size_t)e * KDIM * NDIM;
        if constexpr (MODE == 1) { Wh = g_rW1h + off; Wl = g_rW1l + off; }
        else                     { Wh = g_rW2h + off; Wl = g_rW2l + off; }
        bb = bias + e * NDIM;
    }
    const __nv_bfloat16 *Agh, *Agl;
    if constexpr (MODE <= 1)      { Agh = g_Xh;  Agl = g_Xl; }
    else if constexpr (MODE == 2) { Agh = g_Hsh; Agl = g_Hsl; }
    else                          { Agh = g_Hrh; Agl = g_Hrl; }

    if (tid < BM) {
        int r = rowTile + tid;
        if constexpr (MODE == 1) s_row[tid] = g_perm[r];
        else                     s_row[tid] = r;
        if constexpr (MODE == 3) { s_tok[tid] = g_perm[r]; s_w[tid] = g_wgt[r]; }
    }
    __syncthreads();

    const int lane = tid & 31, warp = tid >> 5;
    const int wm = warp >> 2;   // 0..1 -> 64 rows each
    const int wn = warp & 3;    // 0..3 -> 32 cols each

    // staging (global->reg->smem)
    const int aR = tid >> 1,  aC = (tid & 1) * 8;
    const int bR = tid >> 4,  bC = (tid & 15) * 8;
    const size_t arow = (size_t)s_row[aR];
    const __nv_bfloat16* Aph = Agh + arow * KDIM + aC;
    const __nv_bfloat16* Apl = Agl + arow * KDIM + aC;
    const __nv_bfloat16* Bph = Wh + (size_t)bR * NDIM + colTile + bC;
    const __nv_bfloat16* Bpl = Wl + (size_t)bR * NDIM + colTile + bC;

    // ldmatrix lane addresses
    uint32_t sAaddr = (uint32_t)__cvta_generic_to_shared(
        &sA[0][0][wm * 64 + (lane & 15)][(lane >> 4) * 8]);
    uint32_t sBaddr = (uint32_t)__cvta_generic_to_shared(
        &sB[0][0][(lane & 7) + ((lane >> 3) & 1) * 8][wn * 32 + (lane >> 4) * 8]);
    constexpr uint32_t A_HL = 128 * 24 * 2;
    constexpr uint32_t A_STAGE = 2 * A_HL;
    constexpr uint32_t B_HL = 16 * 136 * 2;
    constexpr uint32_t B_STAGE = 2 * B_HL;

    float acc[4][4][4] = {};
    uint4 rAh, rAl, rBh, rBl;

    // prologue: stage 0
    rAh = *reinterpret_cast<const uint4*>(Aph);
    rAl = *reinterpret_cast<const uint4*>(Apl);
    rBh = *reinterpret_cast<const uint4*>(Bph);
    rBl = *reinterpret_cast<const uint4*>(Bpl);
    *reinterpret_cast<uint4*>(&sA[0][0][aR][aC]) = rAh;
    *reinterpret_cast<uint4*>(&sA[0][1][aR][aC]) = rAl;
    *reinterpret_cast<uint4*>(&sB[0][0][bR][bC]) = rBh;
    *reinterpret_cast<uint4*>(&sB[0][1][bR][bC]) = rBl;
    __syncthreads();

    int st = 0;
    for (int kt = 0; kt < KDIM; kt += 16) {
        const bool more = (kt + 16 < KDIM);
        if (more) {
            rAh = *reinterpret_cast<const uint4*>(Aph + kt + 16);
            rAl = *reinterpret_cast<const uint4*>(Apl + kt + 16);
            rBh = *reinterpret_cast<const uint4*>(Bph + (size_t)(kt + 16) * NDIM);
            rBl = *reinterpret_cast<const uint4*>(Bpl + (size_t)(kt + 16) * NDIM);
        }
        uint32_t aH[4][4], aL[4][4], bH[2][4], bL[2][4];
#pragma unroll
        for (int mi = 0; mi < 4; mi++) {
            ldsm4(aH[mi], sAaddr + st * A_STAGE + mi * (16 * 24 * 2));
            ldsm4(aL[mi], sAaddr + st * A_STAGE + A_HL + mi * (16 * 24 * 2));
        }
#pragma unroll
        for (int p = 0; p < 2; p++) {
            ldsm4t(bH[p], sBaddr + st * B_STAGE + p * (16 * 2));
            ldsm4t(bL[p], sBaddr + st * B_STAGE + B_HL + p * (16 * 2));
        }
#pragma unroll
        for (int mi = 0; mi < 4; mi++)
#pragma unroll
            for (int ni = 0; ni < 4; ni++) {
                const int p = ni >> 1, q = (ni & 1) * 2;
                mma_bf16(acc[mi][ni], aH[mi], bH[p][q], bH[p][q + 1]);
                mma_bf16(acc[mi][ni], aH[mi], bL[p][q], bL[p][q + 1]);
                mma_bf16(acc[mi][ni], aL[mi], bH[p][q], bH[p][q + 1]);
            }
        if (more) {
            *reinterpret_cast<uint4*>(&sA[st ^ 1][0][aR][aC]) = rAh;
            *reinterpret_cast<uint4*>(&sA[st ^ 1][1][aR][aC]) = rAl;
            *reinterpret_cast<uint4*>(&sB[st ^ 1][0][bR][bC]) = rBh;
            *reinterpret_cast<uint4*>(&sB[st ^ 1][1][bR][bC]) = rBl;
        }
        st ^= 1;
        __syncthreads();
    }

    // epilogue
    const int r0 = lane >> 2, c0 = (lane & 3) * 2;
#pragma unroll
    for (int mi = 0; mi < 4; mi++) {
#pragma unroll
        for (int rr = 0; rr < 2; rr++) {
            const int m = wm * 64 + mi * 16 + r0 + rr * 8;
            const int grow = rowTile + m;
#pragma unroll
            for (int ni = 0; ni < 4; ni++) {
                const int col = colTile + wn * 32 + ni * 8 + c0;
                float v0 = acc[mi][ni][rr * 2 + 0] + bb[col];
                float v1 = acc[mi][ni][rr * 2 + 1] + bb[col + 1];
                if constexpr (MODE <= 1) {
                    v0 = silu(v0); v1 = silu(v1);
                    __nv_bfloat16 h0 = __float2bfloat16(v0);
                    __nv_bfloat16 h1 = __float2bfloat16(v1);
                    __nv_bfloat16 l0 = __float2bfloat16(v0 - __bfloat162float(h0));
                    __nv_bfloat16 l1 = __float2bfloat16(v1 - __bfloat162float(h1));
                    __nv_bfloat16* Hh = (MODE == 0 ? g_Hsh : g_Hrh);
                    __nv_bfloat16* Hl = (MODE == 0 ? g_Hsl : g_Hrl);
                    *reinterpret_cast<__nv_bfloat162*>(Hh + (size_t)grow * NDIM + col)
                        = __halves2bfloat162(h0, h1);
                    *reinterpret_cast<__nv_bfloat162*>(Hl + (size_t)grow * NDIM + col)
                        = __halves2bfloat162(l0, l1);
                } else if constexpr (MODE == 2) {
                    *reinterpret_cast<float2*>(out + (size_t)grow * NDIM + col)
                        = make_float2(v0, v1);
                } else {
                    const float w = s_w[m];
                    float* dst = out + (size_t)s_tok[m] * NDIM + col;
                    atomicAdd(dst + 0, w * v0);
                    atomicAdd(dst + 1, w * v1);
                }
            }
        }
    }
}

// plain (non-template) launch wrappers
__global__ void __launch_bounds__(256) gemm_m0(const float* __restrict__ bias) {
    mma_gemm_body<0, D, HD>(bias, nullptr);
}
__global__ void __launch_bounds__(256) gemm_m1(const float* __restrict__ bias) {
    mma_gemm_body<1, D, HD>(bias, nullptr);
}
__global__ void __launch_bounds__(256) gemm_m2(const float* __restrict__ bias,
                                               float* __restrict__ out) {
    mma_gemm_body<2, HD, D>(bias, out);
}
__global__ void __launch_bounds__(256) gemm_m3(const float* __restrict__ bias,
                                               float* __restrict__ out) {
    mma_gemm_body<3, HD, D>(bias, out);
}

extern "C" void kernel_launch(void* const* d_in, const int* in_sizes, int n_in,
                              void* d_out, int out_size) {
    (void)in_sizes; (void)n_in; (void)out_size;
    const float* X   = (const float*)d_in[0];
    const float* RW  = (const float*)d_in[1];
    const float* EB  = (const float*)d_in[2];
    const float* sW1 = (const float*)d_in[3];
    const float* sb1 = (const float*)d_in[4];
    const float* sW2 = (const float*)d_in[5];
    const float* sb2 = (const float*)d_in[6];
    const float* rW1 = (const float*)d_in[7];
    const float* rb1 = (const float*)d_in[8];
    const float* rW2 = (const float*)d_in[9];
    const float* rb2 = (const float*)d_in[10];
    float* out = (float*)d_out;

    init_kernel<<<(CAP + 255) / 256, 256>>>();
    routing_kernel<<<NTOK / 8, 256>>>(X, RW, EB);
    prefix_kernel<<<1, 32>>>();
    scatter_kernel<<<(NTOK * 2) / 256, 256>>>();

    cvt_kernel<<<(NTOK * D / 2 + 255) / 256, 256>>>(X, NTOK * D, 0);
    cvt_kernel<<<(D * HD / 2 + 255) / 256, 256>>>(sW1, D * HD, 1);
    cvt_kernel<<<(HD * D / 2 + 255) / 256, 256>>>(sW2, HD * D, 2);
    cvt_kernel<<<(NE * D * HD / 2 + 255) / 256, 256>>>(rW1, NE * D * HD, 3);
    cvt_kernel<<<(NE * HD * D / 2 + 255) / 256, 256>>>(rW2, NE * HD * D, 4);

    gemm_m0<<<dim3(HD / BN, NTOK / BM), 256>>>(sb1);
    gemm_m1<<<dim3(HD / BN, CAP / BM), 256>>>(rb1);
    gemm_m2<<<dim3(D / BN, NTOK / BM), 256>>>(sb2, out);
    gemm_m3<<<dim3(D / BN, CAP / BM), 256>>>(rb2, out);
}

// round 5
// speedup vs baseline: 2.5732x; 1.1475x over previous
#include <cuda_runtime.h>
#include <cuda_bf16.h>
#include <cstdint>
#include <math.h>

// tcgen05 is only available in arch-specific (sm_103a) or family compilation.
#if defined(__CUDA_ARCH__) && (defined(__CUDA_ARCH_FEAT_SM103_ALL) || \
    defined(__CUDA_ARCH_FEAT_SM100_ALL) || defined(__CUDA_ARCH_SPECIFIC__) || \
    defined(__CUDA_ARCH_FAMILY_SPECIFIC__))
#define TC_OK 1
#else
#define TC_OK 0
#endif

namespace {
constexpr int NTOK = 8192;
constexpr int D    = 1024;
constexpr int HD   = 512;
constexpr int NE   = 8;
constexpr int BM = 128, BN = 128;
constexpr int CAP  = 17408;            // 2*NTOK + per-expert pad to 128

// tcgen05 dynamic smem layout (bytes)
constexpr int OFF_TMEM  = 0;
constexpr int OFF_MBAR  = 16;
constexpr int OFF_ROW   = 32;
constexpr int OFF_TOK   = 544;
constexpr int OFF_W     = 1056;
constexpr int OFF_TILES = 2048;
constexpr int TILE_B    = 128 * 64 * 2;     // 16384 B
constexpr int STAGE_B   = 4 * TILE_B;       // Ah,Al,Bh,Bl
constexpr int SMEM_BYTES = OFF_TILES + 2 * STAGE_B;   // 133120

// idesc: F32 accum, BF16 a/b, N=128, M=128, K-major both
constexpr uint32_t IDESC = (1u << 4) | (1u << 7) | (1u << 10)
                         | ((BN / 8) << 17) | ((BM / 16) << 24);
constexpr uint64_t DESC_BASE_SW128 =
    (uint64_t(2)  << 61) | (uint64_t(1) << 46)
  | (uint64_t(64) << 32) | (uint64_t(1) << 16);
}

__device__ int   g_use_tc;
__device__ int   g_counts[NE];
__device__ int   g_offsets[NE + 1];
__device__ int   g_cursor[NE];
__device__ int   g_perm[CAP];
__device__ float g_wgt[CAP];
__device__ int   g_tok_e[NTOK * 2];
__device__ float g_tok_w[NTOK * 2];

// shared operands (both paths): X and hidden activations, row-major [*,K]
__device__ __align__(16) __nv_bfloat16 g_Xh[NTOK * D],  g_Xl[NTOK * D];
__device__ __align__(16) __nv_bfloat16 g_Hsh[NTOK * HD], g_Hsl[NTOK * HD];
__device__ __align__(16) __nv_bfloat16 g_Hrh[(size_t)CAP * HD], g_Hrl[(size_t)CAP * HD];

// tcgen05 weights: TRANSPOSED [N,K] K-major
__device__ __align__(16) __nv_bfloat16 g_tW1h[HD * D],  g_tW1l[HD * D];
__device__ __align__(16) __nv_bfloat16 g_tW2h[D * HD],  g_tW2l[D * HD];
__device__ __align__(16) __nv_bfloat16 g_tr1h[NE * HD * D], g_tr1l[NE * HD * D];
__device__ __align__(16) __nv_bfloat16 g_tr2h[NE * D * HD], g_tr2l[NE * D * HD];

// fallback weights: original [K,N]
__device__ __align__(16) __nv_bfloat16 g_fW1h[D * HD],  g_fW1l[D * HD];
__device__ __align__(16) __nv_bfloat16 g_fW2h[HD * D],  g_fW2l[HD * D];
__device__ __align__(16) __nv_bfloat16 g_fr1h[NE * D * HD], g_fr1l[NE * D * HD];
__device__ __align__(16) __nv_bfloat16 g_fr2h[NE * HD * D], g_fr2l[NE * HD * D];

// ---------------- routing / bookkeeping (shared) ----------------

__global__ void init_kernel() {
    int i = blockIdx.x * blockDim.x + threadIdx.x;
    if (i == 0) g_use_tc = TC_OK;
    if (i < NE) g_counts[i] = 0;
    if (i < CAP) { g_perm[i] = 0; g_wgt[i] = 0.0f; }
}

__global__ void routing_kernel(const float* __restrict__ X,
                               const float* __restrict__ RW,
                               const float* __restrict__ EB) {
    int warp = (blockIdx.x * blockDim.x + threadIdx.x) >> 5;
    int lane = threadIdx.x & 31;
    if (warp >= NTOK) return;
    const float* x = X + (size_t)warp * D;
    float acc[NE];
#pragma unroll
    for (int e = 0; e < NE; e++) acc[e] = 0.0f;
    for (int k = lane; k < D; k += 32) {
        float xv = x[k];
#pragma unroll
        for (int e = 0; e < NE; e++) acc[e] = fmaf(xv, RW[e * D + k], acc[e]);
    }
#pragma unroll
    for (int e = 0; e < NE; e++) {
#pragma unroll
        for (int o = 16; o > 0; o >>= 1)
            acc[e] += __shfl_down_sync(0xffffffffu, acc[e], o);
    }
    if (lane == 0) {
        float act[NE];
#pragma unroll
        for (int e = 0; e < NE; e++) {
            float l = acc[e] + EB[e];
            float sp = (l > 0.0f) ? (l + log1pf(expf(-l))) : log1pf(expf(l));
            act[e] = sqrtf(sp);
        }
        int i0 = 0;
#pragma unroll
        for (int e = 1; e < NE; e++) if (act[e] > act[i0]) i0 = e;
        int i1 = (i0 == 0) ? 1 : 0;
#pragma unroll
        for (int e = 0; e < NE; e++)
            if (e != i0 && act[e] > act[i1]) i1 = e;
        g_tok_e[2 * warp + 0] = i0; g_tok_w[2 * warp + 0] = act[i0];
        g_tok_e[2 * warp + 1] = i1; g_tok_w[2 * warp + 1] = act[i1];
        atomicAdd(&g_counts[i0], 1);
        atomicAdd(&g_counts[i1], 1);
    }
}

__global__ void prefix_kernel() {
    if (threadIdx.x == 0 && blockIdx.x == 0) {
        int off = 0;
        for (int e = 0; e < NE; e++) {
            g_offsets[e] = off;
            g_cursor[e]  = off;
            off += ((g_counts[e] + BM - 1) / BM) * BM;
        }
        g_offsets[NE] = off;
    }
}

__global__ void scatter_kernel() {
    int i = blockIdx.x * blockDim.x + threadIdx.x;
    if (i >= NTOK * 2) return;
    int e = g_tok_e[i];
    int slot = atomicAdd(&g_cursor[e], 1);
    g_perm[slot] = i >> 1;
    g_wgt[slot]  = g_tok_w[i];
}

__global__ void cvt_x_kernel(const float* __restrict__ src, int n) {
    int i = (blockIdx.x * blockDim.x + threadIdx.x) * 2;
    if (i >= n) return;
    float2 v = *reinterpret_cast<const float2*>(src + i);
    __nv_bfloat16 h0 = __float2bfloat16(v.x);
    __nv_bfloat16 h1 = __float2bfloat16(v.y);
    __nv_bfloat16 l0 = __float2bfloat16(v.x - __bfloat162float(h0));
    __nv_bfloat16 l1 = __float2bfloat16(v.y - __bfloat162float(h1));
    *reinterpret_cast<__nv_bfloat162*>(g_Xh + i) = __halves2bfloat162(h0, h1);
    *reinterpret_cast<__nv_bfloat162*>(g_Xl + i) = __halves2bfloat162(l0, l1);
}

// fallback cvt: [K,N] fp32 -> hi/lo bf16 same layout (gated: only when !tc)
__global__ void fb_cvt_kernel(const float* __restrict__ src, int n, int sel) {
    if (g_use_tc) return;
    int i = (blockIdx.x * blockDim.x + threadIdx.x) * 2;
    if (i >= n) return;
    float2 v = *reinterpret_cast<const float2*>(src + i);
    __nv_bfloat16 h0 = __float2bfloat16(v.x);
    __nv_bfloat16 h1 = __float2bfloat16(v.y);
    __nv_bfloat16 l0 = __float2bfloat16(v.x - __bfloat162float(h0));
    __nv_bfloat16 l1 = __float2bfloat16(v.y - __bfloat162float(h1));
    __nv_bfloat16 *hp, *lp;
    switch (sel) {
        case 1:  hp = g_fW1h; lp = g_fW1l; break;
        case 2:  hp = g_fW2h; lp = g_fW2l; break;
        case 3:  hp = g_fr1h; lp = g_fr1l; break;
        default: hp = g_fr2h; lp = g_fr2l; break;
    }
    *reinterpret_cast<__nv_bfloat162*>(hp + i) = __halves2bfloat162(h0, h1);
    *reinterpret_cast<__nv_bfloat162*>(lp + i) = __halves2bfloat162(l0, l1);
}

// tcgen05 cvt: [K,N] fp32 -> [N,K] hi/lo bf16 transposed (gated: only when tc)
__global__ void tc_cvt_t_kernel(const float* __restrict__ src, int K, int N, int sel) {
    if (!g_use_tc) return;
    __shared__ float t[32][33];
    const int e  = blockIdx.z;
    const int k0 = blockIdx.y * 32, n0 = blockIdx.x * 32;
    const float* s = src + (size_t)e * K * N;
    const int tx = threadIdx.x, ty = threadIdx.y;   // 32 x 8
#pragma unroll
    for (int j = 0; j < 4; j++)
        t[ty + j * 8][tx] = s[(size_t)(k0 + ty + j * 8) * N + n0 + tx];
    __syncthreads();
    __nv_bfloat16 *hp, *lp;
    switch (sel) {
        case 1:  hp = g_tW1h; lp = g_tW1l; break;
        case 2:  hp = g_tW2h; lp = g_tW2l; break;
        case 3:  hp = g_tr1h; lp = g_tr1l; break;
        default: hp = g_tr2h; lp = g_tr2l; break;
    }
    hp += (size_t)e * N * K;  lp += (size_t)e * N * K;
#pragma unroll
    for (int j = 0; j < 4; j++) {
        float v = t[tx][ty + j * 8];
        __nv_bfloat16 h = __float2bfloat16(v);
        __nv_bfloat16 l = __float2bfloat16(v - __bfloat162float(h));
        size_t idx = (size_t)(n0 + ty + j * 8) * K + k0 + tx;
        hp[idx] = h;  lp[idx] = l;
    }
}

__device__ __forceinline__ float silu(float v) { return v / (1.0f + expf(-v)); }

// ================= fallback path (mma.sync, verbatim from R3) =================

__device__ __forceinline__ void ldsm4(uint32_t (&r)[4], uint32_t addr) {
    asm volatile("ldmatrix.sync.aligned.m8n8.x4.shared.b16 {%0,%1,%2,%3}, [%4];\n"
        : "=r"(r[0]), "=r"(r[1]), "=r"(r[2]), "=r"(r[3]) : "r"(addr));
}
__device__ __forceinline__ void ldsm4t(uint32_t (&r)[4], uint32_t addr) {
    asm volatile("ldmatrix.sync.aligned.m8n8.x4.trans.shared.b16 {%0,%1,%2,%3}, [%4];\n"
        : "=r"(r[0]), "=r"(r[1]), "=r"(r[2]), "=r"(r[3]) : "r"(addr));
}
__device__ __forceinline__ void mma_bf16(float (&c)[4], const uint32_t (&a)[4],
                                         uint32_t b0, uint32_t b1) {
    asm volatile(
        "mma.sync.aligned.m16n8k16.row.col.f32.bf16.bf16.f32 "
        "{%0,%1,%2,%3}, {%4,%5,%6,%7}, {%8,%9}, {%0,%1,%2,%3};\n"
        : "+f"(c[0]), "+f"(c[1]), "+f"(c[2]), "+f"(c[3])
        : "r"(a[0]), "r"(a[1]), "r"(a[2]), "r"(a[3]), "r"(b0), "r"(b1));
}

template <int MODE, int KDIM, int NDIM>
__device__ __forceinline__ void fb_gemm_body(const float* __restrict__ bias,
                                             float* __restrict__ out) {
    __shared__ __align__(16) __nv_bfloat16 sA[2][2][128][24];
    __shared__ __align__(16) __nv_bfloat16 sB[2][2][16][136];
    __shared__ int   s_row[128];
    __shared__ int   s_tok[128];
    __shared__ float s_w[128];

    const int tid = threadIdx.x;
    const int rowTile = blockIdx.y * BM;
    const int colTile = blockIdx.x * BN;

    const __nv_bfloat16 *Wh, *Wl;
    const float* bb = bias;
    if constexpr (MODE == 0)      { Wh = g_fW1h; Wl = g_fW1l; }
    else if constexpr (MODE == 2) { Wh = g_fW2h; Wl = g_fW2l; }
    else {
        int e = 0;
#pragma unroll
        for (int i = 1; i < NE; i++) if (rowTile >= g_offsets[i]) e = i;
        size_t off = (size_t)e * KDIM * NDIM;
        if constexpr (MODE == 1) { Wh = g_fr1h + off; Wl = g_fr1l + off; }
        else                     { Wh = g_fr2h + off; Wl = g_fr2l + off; }
        bb = bias + e * NDIM;
    }
    const __nv_bfloat16 *Agh, *Agl;
    if constexpr (MODE <= 1)      { Agh = g_Xh;  Agl = g_Xl; }
    else if constexpr (MODE == 2) { Agh = g_Hsh; Agl = g_Hsl; }
    else                          { Agh = g_Hrh; Agl = g_Hrl; }

    if (tid < BM) {
        int r = rowTile + tid;
        if constexpr (MODE == 1) s_row[tid] = g_perm[r];
        else                     s_row[tid] = r;
        if constexpr (MODE == 3) { s_tok[tid] = g_perm[r]; s_w[tid] = g_wgt[r]; }
    }
    __syncthreads();

    const int lane = tid & 31, warp = tid >> 5;
    const int wm = warp >> 2;
    const int wn = warp & 3;

    const int aR = tid >> 1,  aC = (tid & 1) * 8;
    const int bR = tid >> 4,  bC = (tid & 15) * 8;
    const size_t arow = (size_t)s_row[aR];
    const __nv_bfloat16* Aph = Agh + arow * KDIM + aC;
    const __nv_bfloat16* Apl = Agl + arow * KDIM + aC;
    const __nv_bfloat16* Bph = Wh + (size_t)bR * NDIM + colTile + bC;
    const __nv_bfloat16* Bpl = Wl + (size_t)bR * NDIM + colTile + bC;

    uint32_t sAaddr = (uint32_t)__cvta_generic_to_shared(
        &sA[0][0][wm * 64 + (lane & 15)][(lane >> 4) * 8]);
    uint32_t sBaddr = (uint32_t)__cvta_generic_to_shared(
        &sB[0][0][(lane & 7) + ((lane >> 3) & 1) * 8][wn * 32 + (lane >> 4) * 8]);
    constexpr uint32_t A_HL = 128 * 24 * 2;
    constexpr uint32_t A_STAGE = 2 * A_HL;
    constexpr uint32_t B_HL = 16 * 136 * 2;
    constexpr uint32_t B_STAGE = 2 * B_HL;

    float acc[4][4][4] = {};
    uint4 rAh, rAl, rBh, rBl;

    rAh = *reinterpret_cast<const uint4*>(Aph);
    rAl = *reinterpret_cast<const uint4*>(Apl);
    rBh = *reinterpret_cast<const uint4*>(Bph);
    rBl = *reinterpret_cast<const uint4*>(Bpl);
    *reinterpret_cast<uint4*>(&sA[0][0][aR][aC]) = rAh;
    *reinterpret_cast<uint4*>(&sA[0][1][aR][aC]) = rAl;
    *reinterpret_cast<uint4*>(&sB[0][0][bR][bC]) = rBh;
    *reinterpret_cast<uint4*>(&sB[0][1][bR][bC]) = rBl;
    __syncthreads();

    int st = 0;
    for (int kt = 0; kt < KDIM; kt += 16) {
        const bool more = (kt + 16 < KDIM);
        if (more) {
            rAh = *reinterpret_cast<const uint4*>(Aph + kt + 16);
            rAl = *reinterpret_cast<const uint4*>(Apl + kt + 16);
            rBh = *reinterpret_cast<const uint4*>(Bph + (size_t)(kt + 16) * NDIM);
            rBl = *reinterpret_cast<const uint4*>(Bpl + (size_t)(kt + 16) * NDIM);
        }
        uint32_t aH[4][4], aL[4][4], bH[2][4], bL[2][4];
#pragma unroll
        for (int mi = 0; mi < 4; mi++) {
            ldsm4(aH[mi], sAaddr + st * A_STAGE + mi * (16 * 24 * 2));
            ldsm4(aL[mi], sAaddr + st * A_STAGE + A_HL + mi * (16 * 24 * 2));
        }
#pragma unroll
        for (int p = 0; p < 2; p++) {
            ldsm4t(bH[p], sBaddr + st * B_STAGE + p * (16 * 2));
            ldsm4t(bL[p], sBaddr + st * B_STAGE + B_HL + p * (16 * 2));
        }
#pragma unroll
        for (int mi = 0; mi < 4; mi++)
#pragma unroll
            for (int ni = 0; ni < 4; ni++) {
                const int p = ni >> 1, q = (ni & 1) * 2;
                mma_bf16(acc[mi][ni], aH[mi], bH[p][q], bH[p][q + 1]);
                mma_bf16(acc[mi][ni], aH[mi], bL[p][q], bL[p][q + 1]);
                mma_bf16(acc[mi][ni], aL[mi], bH[p][q], bH[p][q + 1]);
            }
        if (more) {
            *reinterpret_cast<uint4*>(&sA[st ^ 1][0][aR][aC]) = rAh;
            *reinterpret_cast<uint4*>(&sA[st ^ 1][1][aR][aC]) = rAl;
            *reinterpret_cast<uint4*>(&sB[st ^ 1][0][bR][bC]) = rBh;
            *reinterpret_cast<uint4*>(&sB[st ^ 1][1][bR][bC]) = rBl;
        }
        st ^= 1;
        __syncthreads();
    }

    const int r0 = lane >> 2, c0 = (lane & 3) * 2;
#pragma unroll
    for (int mi = 0; mi < 4; mi++) {
#pragma unroll
        for (int rr = 0; rr < 2; rr++) {
            const int m = wm * 64 + mi * 16 + r0 + rr * 8;
            const int grow = rowTile + m;
#pragma unroll
            for (int ni = 0; ni < 4; ni++) {
                const int col = colTile + wn * 32 + ni * 8 + c0;
                float v0 = acc[mi][ni][rr * 2 + 0] + bb[col];
                float v1 = acc[mi][ni][rr * 2 + 1] + bb[col + 1];
                if constexpr (MODE <= 1) {
                    v0 = silu(v0); v1 = silu(v1);
                    __nv_bfloat16 h0 = __float2bfloat16(v0);
                    __nv_bfloat16 h1 = __float2bfloat16(v1);
                    __nv_bfloat16 l0 = __float2bfloat16(v0 - __bfloat162float(h0));
                    __nv_bfloat16 l1 = __float2bfloat16(v1 - __bfloat162float(h1));
                    __nv_bfloat16* Hh = (MODE == 0 ? g_Hsh : g_Hrh);
                    __nv_bfloat16* Hl = (MODE == 0 ? g_Hsl : g_Hrl);
                    *reinterpret_cast<__nv_bfloat162*>(Hh + (size_t)grow * NDIM + col)
                        = __halves2bfloat162(h0, h1);
                    *reinterpret_cast<__nv_bfloat162*>(Hl + (size_t)grow * NDIM + col)
                        = __halves2bfloat162(l0, l1);
                } else if constexpr (MODE == 2) {
                    *reinterpret_cast<float2*>(out + (size_t)grow * NDIM + col)
                        = make_float2(v0, v1);
                } else {
                    const float w = s_w[m];
                    float* dst = out + (size_t)s_tok[m] * NDIM + col;
                    atomicAdd(dst + 0, w * v0);
                    atomicAdd(dst + 1, w * v1);
                }
            }
        }
    }
}

__global__ void __launch_bounds__(256) fb_m0(const float* __restrict__ bias) {
    if (g_use_tc) return;
    fb_gemm_body<0, D, HD>(bias, nullptr);
}
__global__ void __launch_bounds__(256) fb_m1(const float* __restrict__ bias) {
    if (g_use_tc) return;
    fb_gemm_body<1, D, HD>(bias, nullptr);
}
__global__ void __launch_bounds__(256) fb_m2(const float* __restrict__ bias,
                                             float* __restrict__ out) {
    if (g_use_tc) return;
    fb_gemm_body<2, HD, D>(bias, out);
}
__global__ void __launch_bounds__(256) fb_m3(const float* __restrict__ bias,
                                             float* __restrict__ out) {
    if (g_use_tc) return;
    fb_gemm_body<3, HD, D>(bias, out);
}

// ================= tcgen05 path (compiled only in arch-specific pass) =========

#if TC_OK
__device__ __forceinline__ uint32_t smem_u32(const void* p) {
    uint32_t a;
    asm("{ .reg .u64 t; cvta.to.shared.u64 t, %1; cvt.u32.u64 %0, t; }"
        : "=r"(a) : "l"(p));
    return a;
}
__device__ __forceinline__ uint32_t elect_one() {
    uint32_t p;
    asm volatile("{\n\t.reg .pred p;\n\telect.sync _|p, 0xFFFFFFFF;\n\t"
                 "selp.b32 %0, 1, 0, p;\n\t}" : "=r"(p));
    return p;
}
__device__ __forceinline__ uint64_t make_desc(uint32_t addr) {
    return DESC_BASE_SW128 | ((uint64_t)(addr >> 4) & 0x3FFF);
}
__device__ __forceinline__ void mma_f16_ss(uint32_t d, uint64_t a_desc,
                                           uint64_t b_desc, uint32_t idesc,
                                           uint32_t acc) {
    asm volatile(
        "{\n\t.reg .pred p;\n\tsetp.ne.u32 p, %5, 0;\n\t"
        "tcgen05.mma.cta_group::1.kind::f16 [%0], %1, %2, %3, {%4,%4,%4,%4}, p;\n\t}"
        :: "r"(d), "l"(a_desc), "l"(b_desc), "r"(idesc), "r"(0u), "r"(acc)
        : "memory");
}
__device__ __forceinline__ void mbar_init(uint32_t addr, uint32_t cnt) {
    asm volatile("mbarrier.init.shared.b64 [%0], %1;" :: "r"(addr), "r"(cnt) : "memory");
}
__device__ __forceinline__ void mbar_wait(uint32_t addr, uint32_t parity) {
    asm volatile(
        "{\n\t.reg .pred P;\n\t"
        "WL_%=:\n\t"
        "mbarrier.try_wait.parity.acquire.cta.shared::cta.b64 P, [%0], %1, 0x989680;\n\t"
        "@P bra.uni WD_%=;\n\t"
        "bra.uni WL_%=;\n\t"
        "WD_%=:\n\t}"
        :: "r"(addr), "r"(parity) : "memory");
}
__device__ __forceinline__ void tc_commit(uint32_t mbar) {
    asm volatile(
        "tcgen05.commit.cta_group::1.mbarrier::arrive::one.shared::cluster.b64 [%0];"
        :: "r"(mbar) : "memory");
}
__device__ __forceinline__ void tc_alloc(uint32_t slot, uint32_t ncols) {
    asm volatile("tcgen05.alloc.cta_group::1.sync.aligned.shared::cta.b32 [%0], %1;"
                 :: "r"(slot), "r"(ncols) : "memory");
}
__device__ __forceinline__ void tc_dealloc(uint32_t t, uint32_t ncols) {
    asm volatile("tcgen05.dealloc.cta_group::1.sync.aligned.b32 %0, %1;"
                 :: "r"(t), "r"(ncols));
}
__device__ __forceinline__ void tc_relinquish() {
    asm volatile("tcgen05.relinquish_alloc_permit.cta_group::1.sync.aligned;");
}
__device__ __forceinline__ void ldtm32(uint32_t* r, uint32_t addr) {
    asm volatile(
        "tcgen05.ld.sync.aligned.32x32b.x32.b32 "
        "{%0,%1,%2,%3,%4,%5,%6,%7,%8,%9,%10,%11,%12,%13,%14,%15,"
        "%16,%17,%18,%19,%20,%21,%22,%23,%24,%25,%26,%27,%28,%29,%30,%31}, [%32];"
        : "=r"(r[0]),"=r"(r[1]),"=r"(r[2]),"=r"(r[3]),"=r"(r[4]),"=r"(r[5]),
          "=r"(r[6]),"=r"(r[7]),"=r"(r[8]),"=r"(r[9]),"=r"(r[10]),"=r"(r[11]),
          "=r"(r[12]),"=r"(r[13]),"=r"(r[14]),"=r"(r[15]),"=r"(r[16]),"=r"(r[17]),
          "=r"(r[18]),"=r"(r[19]),"=r"(r[20]),"=r"(r[21]),"=r"(r[22]),"=r"(r[23]),
          "=r"(r[24]),"=r"(r[25]),"=r"(r[26]),"=r"(r[27]),"=r"(r[28]),"=r"(r[29]),
          "=r"(r[30]),"=r"(r[31])
        : "r"(addr));
}
__device__ __forceinline__ void tc_wait_ld() {
    asm volatile("tcgen05.wait::ld.sync.aligned;" ::: "memory");
}
__device__ __forceinline__ void fence_async_shared() {
    asm volatile("fence.proxy.async.shared::cta;" ::: "memory");
}
__device__ __forceinline__ void tc_fence_after() {
    asm volatile("tcgen05.fence::after_thread_sync;" ::: "memory");
}
__device__ __forceinline__ void tc_fence_before() {
    asm volatile("tcgen05.fence::before_thread_sync;" ::: "memory");
}
__device__ __forceinline__ void red_add_v4(float* p, float a, float b, float c, float d) {
    asm volatile("red.global.add.v4.f32 [%0], {%1,%2,%3,%4};"
                 :: "l"(p), "f"(a), "f"(b), "f"(c), "f"(d) : "memory");
}

template <int MODE, int KD, int NDIM>
__device__ __forceinline__ void tc_gemm_body(const float* __restrict__ bias,
                                             float* __restrict__ out) {
    extern __shared__ __align__(1024) char sm[];
    const uint32_t smb = smem_u32(sm);
    const int tid = threadIdx.x;               // 256
    const int wid = tid >> 5, lane = tid & 31;
    const int rowTile = blockIdx.y * BM;
    const int colTile = blockIdx.x * BN;

    int*   s_row = reinterpret_cast<int*>(sm + OFF_ROW);
    int*   s_tok = reinterpret_cast<int*>(sm + OFF_TOK);
    float* s_w   = reinterpret_cast<float*>(sm + OFF_W);

    const __nv_bfloat16 *Agh, *Agl, *Bgh, *Bgl;
    const float* bb = bias;
    if constexpr (MODE == 0)      { Agh = g_Xh;  Agl = g_Xl;  Bgh = g_tW1h; Bgl = g_tW1l; }
    else if constexpr (MODE == 2) { Agh = g_Hsh; Agl = g_Hsl; Bgh = g_tW2h; Bgl = g_tW2l; }
    else {
        int e = 0;
#pragma unroll
        for (int i = 1; i < NE; i++) if (rowTile >= g_offsets[i]) e = i;
        size_t off = (size_t)e * KD * NDIM;
        if constexpr (MODE == 1) { Agh = g_Xh;  Agl = g_Xl;  Bgh = g_tr1h + off; Bgl = g_tr1l + off; }
        else                     { Agh = g_Hrh; Agl = g_Hrl; Bgh = g_tr2h + off; Bgl = g_tr2l + off; }
        bb = bias + e * NDIM;
    }

    if (tid == 0) { mbar_init(smb + OFF_MBAR, 1); mbar_init(smb + OFF_MBAR + 8, 1); }
    if (tid < BM) {
        int r = rowTile + tid;
        if constexpr (MODE == 1) s_row[tid] = g_perm[r];
        else                     s_row[tid] = r;
        if constexpr (MODE == 3) { s_tok[tid] = g_perm[r]; s_w[tid] = g_wgt[r]; }
    }
    if (wid == 0) tc_alloc(smb + OFF_TMEM, 128);
    __syncthreads();
    if (wid == 0) tc_relinquish();
    const uint32_t tmem = *reinterpret_cast<uint32_t*>(sm + OFF_TMEM);

    // per-thread fill pointers: 4 x 16B vectors per buffer per 64-K chunk
    const __nv_bfloat16 *pAh[4], *pAl[4], *pBh[4], *pBl[4];
    int sws[4];
#pragma unroll
    for (int it = 0; it < 4; it++) {
        int idx = tid + it * 256;
        int r = idx >> 3, c = idx & 7;
        int off = r * 128 + c * 16;
        sws[it] = off ^ ((off >> 3) & 0x70);      // SW128 swizzle
        int ar = s_row[r];
        pAh[it] = Agh + (size_t)ar * KD + c * 8;
        pAl[it] = Agl + (size_t)ar * KD + c * 8;
        int br = colTile + r;
        pBh[it] = Bgh + (size_t)br * KD + c * 8;
        pBl[it] = Bgl + (size_t)br * KD + c * 8;
    }

    constexpr int NCH = KD / 64;
    uint32_t ph0 = 0, ph1 = 0;
    for (int i = 0; i < NCH; i++) {
        const int s = i & 1;
        if (i >= 2) {
            if (s == 0) { mbar_wait(smb + OFF_MBAR, ph0);     ph0 ^= 1; }
            else        { mbar_wait(smb + OFF_MBAR + 8, ph1); ph1 ^= 1; }
        }
        const int kt = i * 64;
        char* tb = sm + OFF_TILES + s * STAGE_B;
#pragma unroll
        for (int it = 0; it < 4; it++) {
            *reinterpret_cast<uint4*>(tb + 0 * TILE_B + sws[it]) =
                *reinterpret_cast<const uint4*>(pAh[it] + kt);
            *reinterpret_cast<uint4*>(tb + 1 * TILE_B + sws[it]) =
                *reinterpret_cast<const uint4*>(pAl[it] + kt);
            *reinterpret_cast<uint4*>(tb + 2 * TILE_B + sws[it]) =
                *reinterpret_cast<const uint4*>(pBh[it] + kt);
            *reinterpret_cast<uint4*>(tb + 3 * TILE_B + sws[it]) =
                *reinterpret_cast<const uint4*>(pBl[it] + kt);
        }
        fence_async_shared();
        __syncthreads();
        if (wid == 0) {
            tc_fence_after();
            if (elect_one()) {
                const uint32_t base = smb + OFF_TILES + s * STAGE_B;
                const uint64_t dAh = make_desc(base);
                const uint64_t dAl = make_desc(base + 1 * TILE_B);
                const uint64_t dBh = make_desc(base + 2 * TILE_B);
                const uint64_t dBl = make_desc(base + 3 * TILE_B);
#pragma unroll
                for (int st = 0; st < 4; st++) {
                    const uint64_t ko = 2 * st;
                    uint32_t acc0 = (i == 0 && st == 0) ? 0u : 1u;
                    mma_f16_ss(tmem, dAh + ko, dBh + ko, IDESC, acc0);
                    mma_f16_ss(tmem, dAh + ko, dBl + ko, IDESC, 1u);
                    mma_f16_ss(tmem, dAl + ko, dBh + ko, IDESC, 1u);
                }
                tc_commit(smb + OFF_MBAR + s * 8);
            }
        }
    }
    mbar_wait(smb + OFF_MBAR, ph0);
    mbar_wait(smb + OFF_MBAR + 8, ph1);
    tc_fence_after();

    // epilogue: warp w -> rows (w&3)*32+lane; cols (w>>2)*64 in two 32-chunks
    const int c0 = (wid >> 2) * 64;
    const uint32_t woff = (uint32_t)(wid & 3) << 21;
    const int m = (wid & 3) * 32 + lane;
    const int grow = rowTile + m;

#pragma unroll
    for (int h = 0; h < 2; h++) {
        const int cb = c0 + h * 32;
        uint32_t r[32];
        ldtm32(r, tmem + woff + cb);
        tc_wait_ld();
        float bv[32];
#pragma unroll
        for (int j = 0; j < 32; j += 4)
            *reinterpret_cast<float4*>(&bv[j]) =
                *reinterpret_cast<const float4*>(bb + colTile + cb + j);

        if constexpr (MODE <= 1) {
            __nv_bfloat16* Hh = (MODE == 0 ? g_Hsh : g_Hrh);
            __nv_bfloat16* Hl = (MODE == 0 ? g_Hsl : g_Hrl);
#pragma unroll
            for (int j0 = 0; j0 < 32; j0 += 8) {
                uint32_t hh[4], ll[4];
#pragma unroll
                for (int p = 0; p < 8; p += 2) {
                    float a = silu(__uint_as_float(r[j0 + p])     + bv[j0 + p]);
                    float b = silu(__uint_as_float(r[j0 + p + 1]) + bv[j0 + p + 1]);
                    __nv_bfloat16 ha = __float2bfloat16(a);
                    __nv_bfloat16 hb = __float2bfloat16(b);
                    __nv_bfloat16 la = __float2bfloat16(a - __bfloat162float(ha));
                    __nv_bfloat16 lb = __float2bfloat16(b - __bfloat162float(hb));
                    __nv_bfloat162 ph = __halves2bfloat162(ha, hb);
                    __nv_bfloat162 pl = __halves2bfloat162(la, lb);
                    hh[p >> 1] = *reinterpret_cast<uint32_t*>(&ph);
                    ll[p >> 1] = *reinterpret_cast<uint32_t*>(&pl);
                }
                size_t doff = (size_t)grow * NDIM + colTile + cb + j0;
                *reinterpret_cast<uint4*>(Hh + doff) = make_uint4(hh[0], hh[1], hh[2], hh[3]);
                *reinterpret_cast<uint4*>(Hl + doff) = make_uint4(ll[0], ll[1], ll[2], ll[3]);
            }
        } else if constexpr (MODE == 2) {
#pragma unroll
            for (int j0 = 0; j0 < 32; j0 += 4) {
                float4 v = make_float4(
                    __uint_as_float(r[j0])     + bv[j0],
                    __uint_as_float(r[j0 + 1]) + bv[j0 + 1],
                    __uint_as_float(r[j0 + 2]) + bv[j0 + 2],
                    __uint_as_float(r[j0 + 3]) + bv[j0 + 3]);
                *reinterpret_cast<float4*>(out + (size_t)grow * NDIM + colTile + cb + j0) = v;
            }
        } else {
            const float w = s_w[m];
            float* dst = out + (size_t)s_tok[m] * NDIM + colTile + cb;
#pragma unroll
            for (int j0 = 0; j0 < 32; j0 += 4)
                red_add_v4(dst + j0,
                           w * (__uint_as_float(r[j0])     + bv[j0]),
                           w * (__uint_as_float(r[j0 + 1]) + bv[j0 + 1]),
                           w * (__uint_as_float(r[j0 + 2]) + bv[j0 + 2]),
                           w * (__uint_as_float(r[j0 + 3]) + bv[j0 + 3]));
        }
    }
    tc_fence_before();
    __syncthreads();
    if (wid == 0) tc_dealloc(tmem, 128);
}
#endif  // TC_OK

__global__ void __launch_bounds__(256) tc_m0(const float* __restrict__ bias) {
#if TC_OK
    tc_gemm_body<0, D, HD>(bias, nullptr);
#endif
}
__global__ void __launch_bounds__(256) tc_m1(const float* __restrict__ bias) {
#if TC_OK
    tc_gemm_body<1, D, HD>(bias, nullptr);
#endif
}
__global__ void __launch_bounds__(256) tc_m2(const float* __restrict__ bias,
                                             float* __restrict__ out) {
#if TC_OK
    tc_gemm_body<2, HD, D>(bias, out);
#endif
}
__global__ void __launch_bounds__(256) tc_m3(const float* __restrict__ bias,
                                             float* __restrict__ out) {
#if TC_OK
    tc_gemm_body<3, HD, D>(bias, out);
#endif
}

extern "C" void kernel_launch(void* const* d_in, const int* in_sizes, int n_in,
                              void* d_out, int out_size) {
    (void)in_sizes; (void)n_in; (void)out_size;
    const float* X   = (const float*)d_in[0];
    const float* RW  = (const float*)d_in[1];
    const float* EB  = (const float*)d_in[2];
    const float* sW1 = (const float*)d_in[3];
    const float* sb1 = (const float*)d_in[4];
    const float* sW2 = (const float*)d_in[5];
    const float* sb2 = (const float*)d_in[6];
    const float* rW1 = (const float*)d_in[7];
    const float* rb1 = (const float*)d_in[8];
    const float* rW2 = (const float*)d_in[9];
    const float* rb2 = (const float*)d_in[10];
    float* out = (float*)d_out;

    cudaFuncSetAttribute(tc_m0, cudaFuncAttributeMaxDynamicSharedMemorySize, SMEM_BYTES);
    cudaFuncSetAttribute(tc_m1, cudaFuncAttributeMaxDynamicSharedMemorySize, SMEM_BYTES);
    cudaFuncSetAttribute(tc_m2, cudaFuncAttributeMaxDynamicSharedMemorySize, SMEM_BYTES);
    cudaFuncSetAttribute(tc_m3, cudaFuncAttributeMaxDynamicSharedMemorySize, SMEM_BYTES);

    init_kernel<<<(CAP + 255) / 256, 256>>>();
    routing_kernel<<<NTOK / 8, 256>>>(X, RW, EB);
    prefix_kernel<<<1, 32>>>();
    scatter_kernel<<<(NTOK * 2) / 256, 256>>>();

    cvt_x_kernel<<<(NTOK * D / 2 + 255) / 256, 256>>>(X, NTOK * D);
    // tcgen05 layout (gated on g_use_tc inside)
    tc_cvt_t_kernel<<<dim3(HD / 32, D / 32, 1), dim3(32, 8)>>>(sW1, D, HD, 1);
    tc_cvt_t_kernel<<<dim3(D / 32, HD / 32, 1), dim3(32, 8)>>>(sW2, HD, D, 2);
    tc_cvt_t_kernel<<<dim3(HD / 32, D / 32, NE), dim3(32, 8)>>>(rW1, D, HD, 3);
    tc_cvt_t_kernel<<<dim3(D / 32, HD / 32, NE), dim3(32, 8)>>>(rW2, HD, D, 4);
    // fallback layout (gated)
    fb_cvt_kernel<<<(D * HD / 2 + 255) / 256, 256>>>(sW1, D * HD, 1);
    fb_cvt_kernel<<<(HD * D / 2 + 255) / 256, 256>>>(sW2, HD * D, 2);
    fb_cvt_kernel<<<(NE * D * HD / 2 + 255) / 256, 256>>>(rW1, NE * D * HD, 3);
    fb_cvt_kernel<<<(NE * HD * D / 2 + 255) / 256, 256>>>(rW2, NE * HD * D, 4);

    tc_m0<<<dim3(HD / BN, NTOK / BM), 256, SMEM_BYTES>>>(sb1);
    fb_m0<<<dim3(HD / BN, NTOK / BM), 256>>>(sb1);
    tc_m1<<<dim3(HD / BN, CAP / BM), 256, SMEM_BYTES>>>(rb1);
    fb_m1<<<dim3(HD / BN, CAP / BM), 256>>>(rb1);
    tc_m2<<<dim3(D / BN, NTOK / BM), 256, SMEM_BYTES>>>(sb2, out);
    fb_m2<<<dim3(D / BN, NTOK / BM), 256>>>(sb2, out);
    tc_m3<<<dim3(D / BN, CAP / BM), 256, SMEM_BYTES>>>(rb2, out);
    fb_m3<<<dim3(D / BN, CAP / BM), 256>>>(rb2, out);
}